// round 5
// baseline (speedup 1.0000x reference)
#include <cuda_runtime.h>
#include <cuda_bf16.h>
#include <cstdint>

// Problem constants
#define D_FULL   8192
#define K_NNZ    1024
#define NTHREADS 256
#define SMEM_WORDS (D_FULL + (D_FULL >> 5))   // pad 1 word per 32 -> 8448
#define SCALE_F  (1.0f / 90.50966799187808f)  // 1/sqrt(8192)

// padded physical index: one pad word every 32 floats.
// Makes all three pass access patterns bank-conflict-free.
__device__ __forceinline__ int P(int i) { return i + (i >> 5); }

__device__ __forceinline__ void radix32(float v[32]) {
#pragma unroll
    for (int h = 1; h < 32; h <<= 1) {
#pragma unroll
        for (int i = 0; i < 32; i++) {
            if ((i & h) == 0) {
                float a = v[i];
                float b = v[i + h];
                v[i]     = a + b;
                v[i + h] = a - b;
            }
        }
    }
}

__global__ void __launch_bounds__(NTHREADS)
fwht_kernel(const float* __restrict__ u,
            const int*   __restrict__ idx,
            float*       __restrict__ out)
{
    __shared__ float z[SMEM_WORDS];
    const int t   = threadIdx.x;
    const int row = blockIdx.x;

    // ---- Phase 0: zero smem (33 words per thread) ----
#pragma unroll
    for (int i = t; i < SMEM_WORDS; i += NTHREADS)
        z[i] = 0.0f;
    __syncthreads();

    // ---- Phase 1: scatter 1024 values (4 per thread, vectorized loads) ----
    {
        const int4   id = reinterpret_cast<const int4*>(idx)[t];
        const float4 uu = reinterpret_cast<const float4*>(u + (size_t)row * K_NNZ)[t];
        atomicAdd(&z[P(id.x)], uu.x);
        atomicAdd(&z[P(id.y)], uu.y);
        atomicAdd(&z[P(id.z)], uu.z);
        atomicAdd(&z[P(id.w)], uu.w);
    }
    __syncthreads();

    float v[32];

    // ---- Pass A: bits 12..8 (stride 256), radix-32 ----
#pragma unroll
    for (int a = 0; a < 32; a++) v[a] = z[P(t + a * 256)];
    radix32(v);
#pragma unroll
    for (int a = 0; a < 32; a++) z[P(t + a * 256)] = v[a];
    __syncthreads();

    // ---- Pass B: bits 7..3 (stride 8), radix-32 ----
    {
        const int base = (t & 7) | ((t >> 3) << 8);
#pragma unroll
        for (int a = 0; a < 32; a++) v[a] = z[P(base + a * 8)];
        radix32(v);
#pragma unroll
        for (int a = 0; a < 32; a++) z[P(base + a * 8)] = v[a];
    }
    __syncthreads();

    // ---- Pass C: bits 2..0 on 4 contiguous groups of 8, then direct STG ----
    {
        // contiguous 32 logical floats; physical base t*33 + a (contiguous)
        const int pb = t * 33;
#pragma unroll
        for (int a = 0; a < 32; a++) v[a] = z[pb + a];

#pragma unroll
        for (int g = 0; g < 4; g++) {
#pragma unroll
            for (int h = 1; h < 8; h <<= 1) {
#pragma unroll
                for (int i = 0; i < 8; i++) {
                    if ((i & h) == 0) {
                        float a = v[g * 8 + i];
                        float b = v[g * 8 + i + h];
                        v[g * 8 + i]     = a + b;
                        v[g * 8 + i + h] = a - b;
                    }
                }
            }
        }

        float* orow = out + (size_t)row * D_FULL + t * 32;
#pragma unroll
        for (int j = 0; j < 8; j++) {
            float4 st;
            st.x = v[j * 4 + 0] * SCALE_F;
            st.y = v[j * 4 + 1] * SCALE_F;
            st.z = v[j * 4 + 2] * SCALE_F;
            st.w = v[j * 4 + 3] * SCALE_F;
            reinterpret_cast<float4*>(orow)[j] = st;
        }
    }
}

extern "C" void kernel_launch(void* const* d_in, const int* in_sizes, int n_in,
                              void* d_out, int out_size)
{
    const float* u   = (const float*)d_in[0];   // (4, 2048, 1024) fp32
    const int*   idx = (const int*)d_in[1];     // (1024,) int32
    float*       out = (float*)d_out;           // (4, 2048, 8192) fp32

    const int rows = in_sizes[0] / K_NNZ;       // 8192
    fwht_kernel<<<rows, NTHREADS>>>(u, idx, out);
}